// round 10
// baseline (speedup 1.0000x reference)
#include <cuda_runtime.h>
#include <cuda_bf16.h>
#include <cstdint>
#include <cstddef>

// ============================================================================
// Problem constants
// ============================================================================
#define K_DIM  12288
#define KW     (K_DIM / 32)   // 384 packed words per row
#define B_ROWS 8192
#define C_ROWS 1000
#define C_PAD  1024

// GEMM tiling: CTA 128x128, 256 threads, 8x8 outputs/thread
#define BM 128
#define BN 128
#define KC 48                 // k-words per smem chunk (8 groups of 6)
#define NCH (KW / KC)         // 8 chunks
#define A_STAGE_BYTES (KC * BM * 4)   // 24576
#define B_STAGE_BYTES (KC * BN * 4)   // 24576
#define STAGE_BYTES (A_STAGE_BYTES + B_STAGE_BYTES)  // 49152
#define GEMM_SMEM (2 * STAGE_BYTES)   // 98304

// Packed sign bits, k-major: g_Xp[kw][m], g_Wp[kw][n]  (bit=1 <=> value < 0)
__device__ uint32_t g_Xp[(size_t)KW * B_ROWS];   // 12.6 MB
__device__ uint32_t g_Wp[(size_t)KW * C_PAD];    //  1.6 MB

// ============================================================================
// Helpers
// ============================================================================
__device__ __forceinline__ uint32_t smem_u32(const void* p) {
    uint32_t a;
    asm("{ .reg .u64 t; cvta.to.shared.u64 t, %1; cvt.u32.u64 %0, t; }"
        : "=r"(a) : "l"(p));
    return a;
}
__device__ __forceinline__ void cp_async_16(uint32_t smem_dst, const void* gmem_src) {
    asm volatile("cp.async.cg.shared.global [%0], [%1], 16;"
                 :: "r"(smem_dst), "l"(gmem_src) : "memory");
}
__device__ __forceinline__ void cp_async_commit() {
    asm volatile("cp.async.commit_group;" ::: "memory");
}
__device__ __forceinline__ void cp_async_wait1() {
    asm volatile("cp.async.wait_group 1;" ::: "memory");
}
__device__ __forceinline__ void cp_async_wait0() {
    asm volatile("cp.async.wait_group 0;" ::: "memory");
}
__device__ __forceinline__ float4 ldcs4(const float4* p) {
    float4 v;
    asm volatile("ld.global.cs.v4.f32 {%0,%1,%2,%3}, [%4];"
                 : "=f"(v.x), "=f"(v.y), "=f"(v.z), "=f"(v.w) : "l"(p));
    return v;
}
// Carry-save adder primitives: one LOP3 each.
__device__ __forceinline__ uint32_t xor3(uint32_t a, uint32_t b, uint32_t c) {
    uint32_t r;
    asm("lop3.b32 %0, %1, %2, %3, 0x96;" : "=r"(r) : "r"(a), "r"(b), "r"(c));
    return r;
}
__device__ __forceinline__ uint32_t maj3(uint32_t a, uint32_t b, uint32_t c) {
    uint32_t r;
    asm("lop3.b32 %0, %1, %2, %3, 0xE8;" : "=r"(r) : "r"(a), "r"(b), "r"(c));
    return r;
}

// ============================================================================
// Pack kernels: thread t packs word kw0+t of row m (32 consecutive floats).
// Block reads 16 KB contiguous; warp-op j touches 32 consecutive 128B lines;
// 8 independent loads per thread (MLP=8, no sync in loop).
// ============================================================================
__global__ void pack_x_kernel(const float* __restrict__ in) {
    const int kw = blockIdx.x * 128 + threadIdx.x;   // grid.x = 3
    const int m = blockIdx.y;                        // 0..8191
    const float4* p = reinterpret_cast<const float4*>(in + (size_t)m * K_DIM + kw * 32);
    uint32_t w = 0;
#pragma unroll
    for (int j = 0; j < 8; j++) {
        float4 f = ldcs4(p + j);
        w |= (__float_as_uint(f.x) >> 31) << (4 * j + 0);
        w |= (__float_as_uint(f.y) >> 31) << (4 * j + 1);
        w |= (__float_as_uint(f.z) >> 31) << (4 * j + 2);
        w |= (__float_as_uint(f.w) >> 31) << (4 * j + 3);
    }
    g_Xp[(size_t)kw * B_ROWS + m] = w;  // default store: keep packed data in L2
}

__global__ void pack_w_kernel(const float* __restrict__ in) {
    const int kw = blockIdx.x * 128 + threadIdx.x;   // grid.x = 3
    const int n = blockIdx.y;                        // 0..1023
    uint32_t w = 0;
    if (n < C_ROWS) {
        const float4* p = reinterpret_cast<const float4*>(in + (size_t)n * K_DIM + kw * 32);
#pragma unroll
        for (int j = 0; j < 8; j++) {
            float4 f = ldcs4(p + j);
            w |= (__float_as_uint(f.x) >> 31) << (4 * j + 0);
            w |= (__float_as_uint(f.y) >> 31) << (4 * j + 1);
            w |= (__float_as_uint(f.z) >> 31) << (4 * j + 2);
            w |= (__float_as_uint(f.w) >> 31) << (4 * j + 3);
        }
    }
    g_Wp[(size_t)kw * C_PAD + n] = w;
}

// ============================================================================
// Binary GEMM with 6:3 carry-save compression: per 6 xor-words,
//   sum popc = popc(s3) + 2*popc(s4) + 4*popc(c4)   (3 popcs instead of 6)
// where  (s1,c1)=CSA(x0,x1,x2), (s2,c2)=CSA(x3,x4,x5),
//        s3=s1^s2, c3=s1&s2, (s4,c4)=CSA(c1,c2,c3).
// Accumulators packed 2-per-register (lo=cols 0-3, hi=cols 4-7; max 12288<2^16).
// ============================================================================
__global__ void __launch_bounds__(256, 2) bgemm_kernel(float* __restrict__ out) {
    extern __shared__ __align__(16) uint32_t sm[];
    const int tid = threadIdx.x;
    const int ty = tid >> 4;          // 0..15 -> m sub-tile
    const int tx = tid & 15;          // 0..15 -> n sub-tile
    const int m0 = blockIdx.x * BM;
    const int n0 = blockIdx.y * BN;
    const uint32_t smem_base = smem_u32(sm);

    // cp.async slots: A chunk = KC*BM words = 1536 x 16B chunks; 6/thread. Same for B.
    uint32_t aDst[6], bDst[6];
    const uint32_t* aSrc[6];
    const uint32_t* bSrc[6];
#pragma unroll
    for (int j = 0; j < 6; j++) {
        int c = tid + j * 256;
        int row = c >> 5, c32 = c & 31;
        aDst[j] = row * (BM * 4) + c32 * 16;
        bDst[j] = A_STAGE_BYTES + row * (BN * 4) + c32 * 16;
        aSrc[j] = g_Xp + (size_t)row * B_ROWS + m0 + c32 * 4;
        bSrc[j] = g_Wp + (size_t)row * C_PAD + n0 + c32 * 4;
    }

    auto load_stage = [&](int ch, int s) {
        const uint32_t base = smem_base + s * STAGE_BYTES;
        const size_t koffA = (size_t)ch * KC * B_ROWS;
        const size_t koffB = (size_t)ch * KC * C_PAD;
#pragma unroll
        for (int j = 0; j < 6; j++) cp_async_16(base + aDst[j], aSrc[j] + koffA);
#pragma unroll
        for (int j = 0; j < 6; j++) cp_async_16(base + bDst[j], bSrc[j] + koffB);
        cp_async_commit();
    };

    // Packed accumulators: acc[i][j] lo16 = col (tx*8+j), hi16 = col (tx*8+4+j)
    uint32_t acc[8][4];
#pragma unroll
    for (int i = 0; i < 8; i++)
#pragma unroll
        for (int j = 0; j < 4; j++) acc[i][j] = 0;

    load_stage(0, 0);

    for (int ch = 0; ch < NCH; ch++) {
        if (ch + 1 < NCH) {
            load_stage(ch + 1, (ch + 1) & 1);
            cp_async_wait1();
        } else {
            cp_async_wait0();
        }
        __syncthreads();

        const uint32_t* As = sm + (ch & 1) * (STAGE_BYTES / 4);
        const uint32_t* Bs = As + (A_STAGE_BYTES / 4);
        const uint32_t* ap = As + ty * 8;
        const uint32_t* bp = Bs + tx * 8;

#pragma unroll 1
        for (int g = 0; g < KC / 6; g++) {
            const uint32_t* agp = ap + g * 6 * BM;
            const uint32_t* bgp = bp + g * 6 * BN;
#pragma unroll
            for (int ib = 0; ib < 2; ib++) {
                // A fragment: 6 words x 4 m-rows
                uint4 Aw[6];
#pragma unroll
                for (int w = 0; w < 6; w++)
                    Aw[w] = *reinterpret_cast<const uint4*>(agp + w * BM + ib * 4);
#pragma unroll
                for (int jb = 0; jb < 2; jb++) {
                    uint4 Bw[6];
#pragma unroll
                    for (int w = 0; w < 6; w++)
                        Bw[w] = *reinterpret_cast<const uint4*>(bgp + w * BN + jb * 4);
                    const uint32_t* Bf = reinterpret_cast<const uint32_t*>(Bw);
                    const uint32_t* Af = reinterpret_cast<const uint32_t*>(Aw);
#pragma unroll
                    for (int i = 0; i < 4; i++) {
#pragma unroll
                        for (int j = 0; j < 4; j++) {
                            uint32_t x0 = Af[0 * 4 + i] ^ Bf[0 * 4 + j];
                            uint32_t x1 = Af[1 * 4 + i] ^ Bf[1 * 4 + j];
                            uint32_t x2 = Af[2 * 4 + i] ^ Bf[2 * 4 + j];
                            uint32_t x3 = Af[3 * 4 + i] ^ Bf[3 * 4 + j];
                            uint32_t x4 = Af[4 * 4 + i] ^ Bf[4 * 4 + j];
                            uint32_t x5 = Af[5 * 4 + i] ^ Bf[5 * 4 + j];
                            uint32_t s1 = xor3(x0, x1, x2);
                            uint32_t c1 = maj3(x0, x1, x2);
                            uint32_t s2 = xor3(x3, x4, x5);
                            uint32_t c2 = maj3(x3, x4, x5);
                            uint32_t s3 = s1 ^ s2;
                            uint32_t c3 = s1 & s2;
                            uint32_t s4 = xor3(c1, c2, c3);
                            uint32_t c4 = maj3(c1, c2, c3);
                            uint32_t cnt = __popc(s3) + 2 * __popc(s4) + 4 * __popc(c4);
                            acc[ib * 4 + i][j] += (jb ? (cnt << 16) : cnt);
                        }
                    }
                }
            }
        }
        __syncthreads();
    }

    // Epilogue: dot = K - 2*mismatch, exact in fp32. Clip columns to C_ROWS.
    const int colBase = n0 + tx * 8;
    const bool full = (colBase + 7 < C_ROWS);
#pragma unroll
    for (int i = 0; i < 8; i++) {
        float* orow = out + (size_t)(m0 + ty * 8 + i) * C_ROWS + colBase;
        float v[8];
#pragma unroll
        for (int j = 0; j < 4; j++) {
            v[j]     = (float)(K_DIM - 2 * (int)(acc[i][j] & 0xFFFFu));
            v[j + 4] = (float)(K_DIM - 2 * (int)(acc[i][j] >> 16));
        }
        if (full) {
            *reinterpret_cast<float4*>(orow) = make_float4(v[0], v[1], v[2], v[3]);
            *reinterpret_cast<float4*>(orow + 4) = make_float4(v[4], v[5], v[6], v[7]);
        } else {
#pragma unroll
            for (int j = 0; j < 8; j++)
                if (colBase + j < C_ROWS) orow[j] = v[j];
        }
    }
}

// ============================================================================
// Launch
// ============================================================================
extern "C" void kernel_launch(void* const* d_in, const int* in_sizes, int n_in,
                              void* d_out, int out_size) {
    const float* x = (const float*)d_in[0];  // [8192, 12288] fp32
    const float* w = (const float*)d_in[1];  // [1000, 12288] fp32
    float* out = (float*)d_out;              // [8192, 1000] fp32

    {
        dim3 g(KW / 128, B_ROWS);            // (3, 8192)
        pack_x_kernel<<<g, 128>>>(x);
    }
    {
        dim3 g(KW / 128, C_PAD);             // (3, 1024)
        pack_w_kernel<<<g, 128>>>(w);
    }

    static int smem_set = 0;
    if (!smem_set) {
        cudaFuncSetAttribute(bgemm_kernel, cudaFuncAttributeMaxDynamicSharedMemorySize,
                             GEMM_SMEM);
        smem_set = 1;
    }
    dim3 grid(B_ROWS / BM, C_PAD / BN);      // (64, 8)
    bgemm_kernel<<<grid, 256, GEMM_SMEM>>>(out);
}

// round 12
// speedup vs baseline: 1.1269x; 1.1269x over previous
#include <cuda_runtime.h>
#include <cuda_bf16.h>
#include <cstdint>
#include <cstddef>

// ============================================================================
// Problem constants
// ============================================================================
#define K_DIM  12288
#define KW     (K_DIM / 32)   // 384 packed words per row
#define B_ROWS 8192
#define C_ROWS 1000
#define C_PAD  1024

// GEMM tiling: CTA 128x128, 256 threads, 8x8 outputs/thread
#define BM 128
#define BN 128
#define KC 48                 // k-words per smem chunk (8 groups of 6)
#define NCH (KW / KC)         // 8 chunks
#define A_STAGE_BYTES (KC * BM * 4)   // 24576
#define B_STAGE_BYTES (KC * BN * 4)   // 24576
#define STAGE_BYTES (A_STAGE_BYTES + B_STAGE_BYTES)  // 49152
#define GEMM_SMEM (2 * STAGE_BYTES)   // 98304

// Packed sign bits, k-major: g_Xp[kw][m], g_Wp[kw][n]  (bit=1 <=> value < 0)
__device__ uint32_t g_Xp[(size_t)KW * B_ROWS];   // 12.6 MB
__device__ uint32_t g_Wp[(size_t)KW * C_PAD];    //  1.6 MB

// ============================================================================
// Helpers
// ============================================================================
__device__ __forceinline__ uint32_t smem_u32(const void* p) {
    uint32_t a;
    asm("{ .reg .u64 t; cvta.to.shared.u64 t, %1; cvt.u32.u64 %0, t; }"
        : "=r"(a) : "l"(p));
    return a;
}
__device__ __forceinline__ void cp_async_16(uint32_t smem_dst, const void* gmem_src) {
    asm volatile("cp.async.cg.shared.global [%0], [%1], 16;"
                 :: "r"(smem_dst), "l"(gmem_src) : "memory");
}
__device__ __forceinline__ void cp_async_commit() {
    asm volatile("cp.async.commit_group;" ::: "memory");
}
__device__ __forceinline__ void cp_async_wait1() {
    asm volatile("cp.async.wait_group 1;" ::: "memory");
}
__device__ __forceinline__ void cp_async_wait0() {
    asm volatile("cp.async.wait_group 0;" ::: "memory");
}
__device__ __forceinline__ float4 ldcs4(const float4* p) {
    float4 v;
    asm volatile("ld.global.cs.v4.f32 {%0,%1,%2,%3}, [%4];"
                 : "=f"(v.x), "=f"(v.y), "=f"(v.z), "=f"(v.w) : "l"(p));
    return v;
}
// Carry-save adder primitives: one LOP3 each.
__device__ __forceinline__ uint32_t xor3(uint32_t a, uint32_t b, uint32_t c) {
    uint32_t r;
    asm("lop3.b32 %0, %1, %2, %3, 0x96;" : "=r"(r) : "r"(a), "r"(b), "r"(c));
    return r;
}
__device__ __forceinline__ uint32_t maj3(uint32_t a, uint32_t b, uint32_t c) {
    uint32_t r;
    asm("lop3.b32 %0, %1, %2, %3, 0xE8;" : "=r"(r) : "r"(a), "r"(b), "r"(c));
    return r;
}

// ============================================================================
// Pack kernels, smem-staged, 384 threads/block (one block per row):
//   Phase 1: thread t loads float4 q = k*384+t (warp reads 512B contiguous —
//            no L1 wavefront amplification), writes 4-bit sign nibble to smem.
//   Phase 2: thread t (t < 384 = KW exactly) assembles word t from 8 nibbles.
// ============================================================================
__device__ __forceinline__ uint32_t nib4(float4 f) {
    return ((__float_as_uint(f.x) >> 31))
         | ((__float_as_uint(f.y) >> 31) << 1)
         | ((__float_as_uint(f.z) >> 31) << 2)
         | ((__float_as_uint(f.w) >> 31) << 3);
}
__device__ __forceinline__ uint32_t word_from_nib8(uint2 nb) {
    // 8 nibble-bytes -> 32-bit word: byte i contributes bits [4i, 4i+4)
    uint32_t w = 0;
#pragma unroll
    for (int i = 0; i < 4; i++) w |= ((nb.x >> (8 * i)) & 0xFu) << (4 * i);
#pragma unroll
    for (int i = 0; i < 4; i++) w |= ((nb.y >> (8 * i)) & 0xFu) << (16 + 4 * i);
    return w;
}

__global__ void __launch_bounds__(384) pack_x_kernel(const float* __restrict__ in) {
    __shared__ __align__(8) uint8_t nib[K_DIM / 4];   // 3072 nibble-bytes
    const int t = threadIdx.x;                        // 0..383
    const int m = blockIdx.x;
    const float4* p = reinterpret_cast<const float4*>(in + (size_t)m * K_DIM);
#pragma unroll
    for (int k = 0; k < 8; k++) {                     // 8*384 = 3072 float4s
        float4 f = ldcs4(p + k * 384 + t);
        nib[k * 384 + t] = (uint8_t)nib4(f);
    }
    __syncthreads();
    uint2 nb = *reinterpret_cast<const uint2*>(&nib[t * 8]);   // t < 384 = KW
    g_Xp[(size_t)t * B_ROWS + m] = word_from_nib8(nb);
}

__global__ void __launch_bounds__(384) pack_w_kernel(const float* __restrict__ in) {
    __shared__ __align__(8) uint8_t nib[K_DIM / 4];
    const int t = threadIdx.x;
    const int n = blockIdx.x;
    if (n < C_ROWS) {
        const float4* p = reinterpret_cast<const float4*>(in + (size_t)n * K_DIM);
#pragma unroll
        for (int k = 0; k < 8; k++) {
            float4 f = ldcs4(p + k * 384 + t);
            nib[k * 384 + t] = (uint8_t)nib4(f);
        }
        __syncthreads();
        uint2 nb = *reinterpret_cast<const uint2*>(&nib[t * 8]);
        g_Wp[(size_t)t * C_PAD + n] = word_from_nib8(nb);
    } else {
        g_Wp[(size_t)t * C_PAD + n] = 0u;  // pad rows [1000,1024), clipped anyway
    }
}

// ============================================================================
// Binary GEMM with 6:3 carry-save compression: per 6 xor-words,
//   sum popc = popc(s3) + 2*popc(s4) + 4*popc(c4)   (3 popcs instead of 6)
// Register-lean cp.async addressing: 2 base pointers + immediate offsets.
// Accumulators packed 2-per-register (lo=cols 0-3, hi=cols 4-7; max 12288<2^16).
// ============================================================================
__global__ void __launch_bounds__(256, 2) bgemm_kernel(float* __restrict__ out) {
    extern __shared__ __align__(16) uint32_t sm[];
    const int tid = threadIdx.x;
    const int ty = tid >> 4;          // 0..15 -> m sub-tile
    const int tx = tid & 15;          // 0..15 -> n sub-tile
    const int m0 = blockIdx.x * BM;
    const int n0 = blockIdx.y * BN;
    const uint32_t smem_base = smem_u32(sm);

    // cp.async base addressing (affine in slot j: row j*8, same 16B column)
    const uint32_t row0 = (uint32_t)(tid >> 5);      // 0..7
    const uint32_t c32 = (uint32_t)(tid & 31);       // 16B chunk index
    const uint32_t aDst0 = row0 * (BM * 4) + c32 * 16;
    const uint32_t bDst0 = A_STAGE_BYTES + row0 * (BN * 4) + c32 * 16;
    const uint32_t* aSrc0 = g_Xp + (size_t)row0 * B_ROWS + m0 + c32 * 4;
    const uint32_t* bSrc0 = g_Wp + (size_t)row0 * C_PAD + n0 + c32 * 4;

    auto load_stage = [&](int ch, int s) {
        const uint32_t base = smem_base + s * STAGE_BYTES;
        const uint32_t* aS = aSrc0 + (size_t)ch * KC * B_ROWS;
        const uint32_t* bS = bSrc0 + (size_t)ch * KC * C_PAD;
#pragma unroll
        for (int j = 0; j < 6; j++)
            cp_async_16(base + aDst0 + j * (8 * BM * 4), aS + j * (8 * B_ROWS));
#pragma unroll
        for (int j = 0; j < 6; j++)
            cp_async_16(base + bDst0 + j * (8 * BN * 4), bS + j * (8 * C_PAD));
        cp_async_commit();
    };

    // Packed accumulators: acc[i][j] lo16 = col (tx*8+j), hi16 = col (tx*8+4+j)
    uint32_t acc[8][4];
#pragma unroll
    for (int i = 0; i < 8; i++)
#pragma unroll
        for (int j = 0; j < 4; j++) acc[i][j] = 0;

    load_stage(0, 0);

    for (int ch = 0; ch < NCH; ch++) {
        if (ch + 1 < NCH) {
            load_stage(ch + 1, (ch + 1) & 1);
            cp_async_wait1();
        } else {
            cp_async_wait0();
        }
        __syncthreads();

        const uint32_t* As = sm + (ch & 1) * (STAGE_BYTES / 4);
        const uint32_t* Bs = As + (A_STAGE_BYTES / 4);
        const uint32_t* ap = As + ty * 8;
        const uint32_t* bp = Bs + tx * 8;

#pragma unroll 1
        for (int g = 0; g < KC / 6; g++) {
            const uint32_t* agp = ap + g * 6 * BM;
            const uint32_t* bgp = bp + g * 6 * BN;
#pragma unroll
            for (int ib = 0; ib < 2; ib++) {
                // A fragment: 6 words x 4 m-rows (24 regs)
                uint4 Aw[6];
#pragma unroll
                for (int w = 0; w < 6; w++)
                    Aw[w] = *reinterpret_cast<const uint4*>(agp + w * BM + ib * 4);
#pragma unroll
                for (int jb = 0; jb < 2; jb++) {
                    uint4 Bw[6];
#pragma unroll
                    for (int w = 0; w < 6; w++)
                        Bw[w] = *reinterpret_cast<const uint4*>(bgp + w * BN + jb * 4);
                    const uint32_t* Bf = reinterpret_cast<const uint32_t*>(Bw);
                    const uint32_t* Af = reinterpret_cast<const uint32_t*>(Aw);
#pragma unroll
                    for (int i = 0; i < 4; i++) {
#pragma unroll
                        for (int j = 0; j < 4; j++) {
                            uint32_t x0 = Af[0 * 4 + i] ^ Bf[0 * 4 + j];
                            uint32_t x1 = Af[1 * 4 + i] ^ Bf[1 * 4 + j];
                            uint32_t x2 = Af[2 * 4 + i] ^ Bf[2 * 4 + j];
                            uint32_t x3 = Af[3 * 4 + i] ^ Bf[3 * 4 + j];
                            uint32_t x4 = Af[4 * 4 + i] ^ Bf[4 * 4 + j];
                            uint32_t x5 = Af[5 * 4 + i] ^ Bf[5 * 4 + j];
                            uint32_t s1 = xor3(x0, x1, x2);
                            uint32_t c1 = maj3(x0, x1, x2);
                            uint32_t s2 = xor3(x3, x4, x5);
                            uint32_t c2 = maj3(x3, x4, x5);
                            uint32_t s3 = s1 ^ s2;
                            uint32_t c3 = s1 & s2;
                            uint32_t s4 = xor3(c1, c2, c3);
                            uint32_t c4 = maj3(c1, c2, c3);
                            uint32_t cnt = __popc(s3) + 2 * __popc(s4) + 4 * __popc(c4);
                            acc[ib * 4 + i][j] += (jb ? (cnt << 16) : cnt);
                        }
                    }
                }
            }
        }
        __syncthreads();
    }

    // Epilogue: dot = K - 2*mismatch, exact in fp32. Clip columns to C_ROWS.
    const int colBase = n0 + tx * 8;
    const bool full = (colBase + 7 < C_ROWS);
#pragma unroll
    for (int i = 0; i < 8; i++) {
        float* orow = out + (size_t)(m0 + ty * 8 + i) * C_ROWS + colBase;
        float v[8];
#pragma unroll
        for (int j = 0; j < 4; j++) {
            v[j]     = (float)(K_DIM - 2 * (int)(acc[i][j] & 0xFFFFu));
            v[j + 4] = (float)(K_DIM - 2 * (int)(acc[i][j] >> 16));
        }
        if (full) {
            *reinterpret_cast<float4*>(orow) = make_float4(v[0], v[1], v[2], v[3]);
            *reinterpret_cast<float4*>(orow + 4) = make_float4(v[4], v[5], v[6], v[7]);
        } else {
#pragma unroll
            for (int j = 0; j < 8; j++)
                if (colBase + j < C_ROWS) orow[j] = v[j];
        }
    }
}

// ============================================================================
// Launch
// ============================================================================
extern "C" void kernel_launch(void* const* d_in, const int* in_sizes, int n_in,
                              void* d_out, int out_size) {
    const float* x = (const float*)d_in[0];  // [8192, 12288] fp32
    const float* w = (const float*)d_in[1];  // [1000, 12288] fp32
    float* out = (float*)d_out;              // [8192, 1000] fp32

    pack_x_kernel<<<B_ROWS, 384>>>(x);       // one block per row
    pack_w_kernel<<<C_PAD, 384>>>(w);

    static int smem_set = 0;
    if (!smem_set) {
        cudaFuncSetAttribute(bgemm_kernel, cudaFuncAttributeMaxDynamicSharedMemorySize,
                             GEMM_SMEM);
        smem_set = 1;
    }
    dim3 grid(B_ROWS / BM, C_PAD / BN);      // (64, 8)
    bgemm_kernel<<<grid, 256, GEMM_SMEM>>>(out);
}

// round 15
// speedup vs baseline: 1.2430x; 1.1030x over previous
#include <cuda_runtime.h>
#include <cuda_bf16.h>
#include <cstdint>
#include <cstddef>

// ============================================================================
// Problem constants
// ============================================================================
#define K_DIM  12288
#define KW     (K_DIM / 32)   // 384 packed words per row
#define B_ROWS 8192
#define C_ROWS 1000
#define C_PAD  1024

// GEMM tiling: CTA 128x128, 256 threads, 8x8 outputs/thread
#define BM 128
#define BN 128
#define KC 48                 // k-words per smem chunk (8 groups of 6)
#define NCH (KW / KC)         // 8 chunks
#define A_STAGE_BYTES (KC * BM * 4)   // 24576
#define B_STAGE_BYTES (KC * BN * 4)   // 24576
#define STAGE_BYTES (A_STAGE_BYTES + B_STAGE_BYTES)  // 49152
#define GEMM_SMEM (2 * STAGE_BYTES)   // 98304

// Packed sign bits, k-major: g_Xp[kw][m], g_Wp[kw][n]  (bit=1 <=> value < 0)
__device__ uint32_t g_Xp[(size_t)KW * B_ROWS];   // 12.6 MB
__device__ uint32_t g_Wp[(size_t)KW * C_PAD];    //  1.6 MB

// ============================================================================
// Helpers
// ============================================================================
__device__ __forceinline__ uint32_t smem_u32(const void* p) {
    uint32_t a;
    asm("{ .reg .u64 t; cvta.to.shared.u64 t, %1; cvt.u32.u64 %0, t; }"
        : "=r"(a) : "l"(p));
    return a;
}
__device__ __forceinline__ void cp_async_16(uint32_t smem_dst, const void* gmem_src) {
    asm volatile("cp.async.cg.shared.global [%0], [%1], 16;"
                 :: "r"(smem_dst), "l"(gmem_src) : "memory");
}
__device__ __forceinline__ void cp_async_commit() {
    asm volatile("cp.async.commit_group;" ::: "memory");
}
__device__ __forceinline__ void cp_async_wait1() {
    asm volatile("cp.async.wait_group 1;" ::: "memory");
}
__device__ __forceinline__ void cp_async_wait0() {
    asm volatile("cp.async.wait_group 0;" ::: "memory");
}
__device__ __forceinline__ float4 ldcs4(const float4* p) {
    float4 v;
    asm volatile("ld.global.cs.v4.f32 {%0,%1,%2,%3}, [%4];"
                 : "=f"(v.x), "=f"(v.y), "=f"(v.z), "=f"(v.w) : "l"(p));
    return v;
}
// Carry-save adder primitives: one LOP3 each.
__device__ __forceinline__ uint32_t xor3(uint32_t a, uint32_t b, uint32_t c) {
    uint32_t r;
    asm("lop3.b32 %0, %1, %2, %3, 0x96;" : "=r"(r) : "r"(a), "r"(b), "r"(c));
    return r;
}
__device__ __forceinline__ uint32_t maj3(uint32_t a, uint32_t b, uint32_t c) {
    uint32_t r;
    asm("lop3.b32 %0, %1, %2, %3, 0xE8;" : "=r"(r) : "r"(a), "r"(b), "r"(c));
    return r;
}

// ============================================================================
// Pack kernels, smem-staged, 384 threads/block (one block per row)
// ============================================================================
__device__ __forceinline__ uint32_t nib4(float4 f) {
    return ((__float_as_uint(f.x) >> 31))
         | ((__float_as_uint(f.y) >> 31) << 1)
         | ((__float_as_uint(f.z) >> 31) << 2)
         | ((__float_as_uint(f.w) >> 31) << 3);
}
__device__ __forceinline__ uint32_t word_from_nib8(uint2 nb) {
    uint32_t w = 0;
#pragma unroll
    for (int i = 0; i < 4; i++) w |= ((nb.x >> (8 * i)) & 0xFu) << (4 * i);
#pragma unroll
    for (int i = 0; i < 4; i++) w |= ((nb.y >> (8 * i)) & 0xFu) << (16 + 4 * i);
    return w;
}

__global__ void __launch_bounds__(384) pack_x_kernel(const float* __restrict__ in) {
    __shared__ __align__(8) uint8_t nib[K_DIM / 4];   // 3072 nibble-bytes
    const int t = threadIdx.x;                        // 0..383
    const int m = blockIdx.x;
    const float4* p = reinterpret_cast<const float4*>(in + (size_t)m * K_DIM);
#pragma unroll
    for (int k = 0; k < 8; k++) {                     // 8*384 = 3072 float4s
        float4 f = ldcs4(p + k * 384 + t);
        nib[k * 384 + t] = (uint8_t)nib4(f);
    }
    __syncthreads();
    uint2 nb = *reinterpret_cast<const uint2*>(&nib[t * 8]);   // t < 384 = KW
    g_Xp[(size_t)t * B_ROWS + m] = word_from_nib8(nb);
}

__global__ void __launch_bounds__(384) pack_w_kernel(const float* __restrict__ in) {
    __shared__ __align__(8) uint8_t nib[K_DIM / 4];
    const int t = threadIdx.x;
    const int n = blockIdx.x;
    if (n < C_ROWS) {
        const float4* p = reinterpret_cast<const float4*>(in + (size_t)n * K_DIM);
#pragma unroll
        for (int k = 0; k < 8; k++) {
            float4 f = ldcs4(p + k * 384 + t);
            nib[k * 384 + t] = (uint8_t)nib4(f);
        }
        __syncthreads();
        uint2 nb = *reinterpret_cast<const uint2*>(&nib[t * 8]);
        g_Wp[(size_t)t * C_PAD + n] = word_from_nib8(nb);
    } else {
        g_Wp[(size_t)t * C_PAD + n] = 0u;  // pad rows [1000,1024), clipped anyway
    }
}

// ============================================================================
// Binary GEMM, 6:3 carry-save compression, conflict-free B layout.
//
// B smem layout per kw-row (128 words): the two 4-word halves of each n-octet
// are split into half-tiles:  pos = jb*64 + (n_octet)*4 + (n%4),  jb=(n/4)%2.
// Consumer B load for fixed (kw, jb): lane tx reads uint4 at tx*4 words —
// 16 lanes x 16B CONTIGUOUS (each 8-lane LDS phase = 128B, zero conflicts).
// Loop order jb-outer so each B fragment is loaded once (A reloads broadcast).
// ============================================================================
__global__ void __launch_bounds__(256, 2) bgemm_kernel(float* __restrict__ out) {
    extern __shared__ __align__(16) uint32_t sm[];
    const int tid = threadIdx.x;
    const int ty = tid >> 4;          // 0..15 -> m sub-tile
    const int tx = tid & 15;          // 0..15 -> n sub-tile
    const int m0 = blockIdx.x * BM;
    const int n0 = blockIdx.y * BN;
    const uint32_t smem_base = smem_u32(sm);

    // cp.async base addressing (affine in slot j: row j*8, same 16B column)
    const uint32_t row0 = (uint32_t)(tid >> 5);      // 0..7
    const uint32_t c32 = (uint32_t)(tid & 31);       // 16B cell index (4 words)
    const uint32_t aDst0 = row0 * (BM * 4) + c32 * 16;
    // B cell c32 holds words n = c32*4..c32*4+3  ->  jb = c32&1, tx8 = c32>>1
    const uint32_t bDst0 = A_STAGE_BYTES + row0 * (BN * 4)
                         + (((c32 & 1) * 64) + ((c32 >> 1) * 4)) * 4;
    const uint32_t* aSrc0 = g_Xp + (size_t)row0 * B_ROWS + m0 + c32 * 4;
    const uint32_t* bSrc0 = g_Wp + (size_t)row0 * C_PAD + n0 + c32 * 4;

    auto load_stage = [&](int ch, int s) {
        const uint32_t base = smem_base + s * STAGE_BYTES;
        const uint32_t* aS = aSrc0 + (size_t)ch * KC * B_ROWS;
        const uint32_t* bS = bSrc0 + (size_t)ch * KC * C_PAD;
#pragma unroll
        for (int j = 0; j < 6; j++)
            cp_async_16(base + aDst0 + j * (8 * BM * 4), aS + j * (8 * B_ROWS));
#pragma unroll
        for (int j = 0; j < 6; j++)
            cp_async_16(base + bDst0 + j * (8 * BN * 4), bS + j * (8 * C_PAD));
        cp_async_commit();
    };

    // Packed accumulators: acc[i][j] lo16 = col (tx*8+j), hi16 = col (tx*8+4+j)
    uint32_t acc[8][4];
#pragma unroll
    for (int i = 0; i < 8; i++)
#pragma unroll
        for (int j = 0; j < 4; j++) acc[i][j] = 0;

    load_stage(0, 0);

    for (int ch = 0; ch < NCH; ch++) {
        if (ch + 1 < NCH) {
            load_stage(ch + 1, (ch + 1) & 1);
            cp_async_wait1();
        } else {
            cp_async_wait0();
        }
        __syncthreads();

        const uint32_t* As = sm + (ch & 1) * (STAGE_BYTES / 4);
        const uint32_t* Bs = As + (A_STAGE_BYTES / 4);
        const uint32_t* ap = As + ty * 8;
        const uint32_t* bp = Bs + tx * 4;          // contiguous 16B per lane

#pragma unroll 1
        for (int g = 0; g < KC / 6; g++) {
            const uint32_t* agp = ap + g * 6 * BM;
            const uint32_t* bgp = bp + g * 6 * BN;
#pragma unroll
            for (int jb = 0; jb < 2; jb++) {
                // B fragment: 6 words x 4 n-cols (24 regs), loaded ONCE
                uint4 Bw[6];
#pragma unroll
                for (int w = 0; w < 6; w++)
                    Bw[w] = *reinterpret_cast<const uint4*>(bgp + w * BN + jb * 64);
                const uint32_t* Bf = reinterpret_cast<const uint32_t*>(Bw);
#pragma unroll
                for (int ib = 0; ib < 2; ib++) {
                    // A fragment: 6 words x 4 m-rows (broadcast loads)
                    uint4 Aw[6];
#pragma unroll
                    for (int w = 0; w < 6; w++)
                        Aw[w] = *reinterpret_cast<const uint4*>(agp + w * BM + ib * 4);
                    const uint32_t* Af = reinterpret_cast<const uint32_t*>(Aw);
#pragma unroll
                    for (int i = 0; i < 4; i++) {
#pragma unroll
                        for (int j = 0; j < 4; j++) {
                            uint32_t x0 = Af[0 * 4 + i] ^ Bf[0 * 4 + j];
                            uint32_t x1 = Af[1 * 4 + i] ^ Bf[1 * 4 + j];
                            uint32_t x2 = Af[2 * 4 + i] ^ Bf[2 * 4 + j];
                            uint32_t x3 = Af[3 * 4 + i] ^ Bf[3 * 4 + j];
                            uint32_t x4 = Af[4 * 4 + i] ^ Bf[4 * 4 + j];
                            uint32_t x5 = Af[5 * 4 + i] ^ Bf[5 * 4 + j];
                            uint32_t s1 = xor3(x0, x1, x2);
                            uint32_t c1 = maj3(x0, x1, x2);
                            uint32_t s2 = xor3(x3, x4, x5);
                            uint32_t c2 = maj3(x3, x4, x5);
                            uint32_t s3 = s1 ^ s2;
                            uint32_t c3 = s1 & s2;
                            uint32_t s4 = xor3(c1, c2, c3);
                            uint32_t c4 = maj3(c1, c2, c3);
                            uint32_t cnt = __popc(s3) + 2 * __popc(s4) + 4 * __popc(c4);
                            acc[ib * 4 + i][j] += (jb ? (cnt << 16) : cnt);
                        }
                    }
                }
            }
        }
        __syncthreads();
    }

    // Epilogue: dot = K - 2*mismatch, exact in fp32. Clip columns to C_ROWS.
    const int colBase = n0 + tx * 8;
    const bool full = (colBase + 7 < C_ROWS);
#pragma unroll
    for (int i = 0; i < 8; i++) {
        float* orow = out + (size_t)(m0 + ty * 8 + i) * C_ROWS + colBase;
        float v[8];
#pragma unroll
        for (int j = 0; j < 4; j++) {
            v[j]     = (float)(K_DIM - 2 * (int)(acc[i][j] & 0xFFFFu));
            v[j + 4] = (float)(K_DIM - 2 * (int)(acc[i][j] >> 16));
        }
        if (full) {
            *reinterpret_cast<float4*>(orow) = make_float4(v[0], v[1], v[2], v[3]);
            *reinterpret_cast<float4*>(orow + 4) = make_float4(v[4], v[5], v[6], v[7]);
        } else {
#pragma unroll
            for (int j = 0; j < 8; j++)
                if (colBase + j < C_ROWS) orow[j] = v[j];
        }
    }
}

// ============================================================================
// Launch
// ============================================================================
extern "C" void kernel_launch(void* const* d_in, const int* in_sizes, int n_in,
                              void* d_out, int out_size) {
    const float* x = (const float*)d_in[0];  // [8192, 12288] fp32
    const float* w = (const float*)d_in[1];  // [1000, 12288] fp32
    float* out = (float*)d_out;              // [8192, 1000] fp32

    pack_x_kernel<<<B_ROWS, 384>>>(x);       // one block per row
    pack_w_kernel<<<C_PAD, 384>>>(w);

    static int smem_set = 0;
    if (!smem_set) {
        cudaFuncSetAttribute(bgemm_kernel, cudaFuncAttributeMaxDynamicSharedMemorySize,
                             GEMM_SMEM);
        smem_set = 1;
    }
    dim3 grid(B_ROWS / BM, C_PAD / BN);      // (64, 8)
    bgemm_kernel<<<grid, 256, GEMM_SMEM>>>(out);
}